// round 15
// baseline (speedup 1.0000x reference)
#include <cuda_runtime.h>
#include <cuda_fp16.h>
#include <math.h>
#include <stdint.h>

#define NMAX 100000
#define EMAX 1600000
#define FIN 128
#define BSTRIDE 64          // bucket stride (max degree supported)
#define LOG2E 1.4426950408889634f

// ---------------- scratch (static device memory; no allocations) -------------
__device__ int    g_cnt[NMAX];
__device__ int    g_colsrc[(size_t)NMAX * BSTRIDE];
__device__ __half g_w1h[384 * 128];           // [n][k] fp16: Wl1|Wr1|res1W
__device__ __half g_w2h[64 * 128];            // [n][k] fp16: Wl2|Wr2|res2W|skipW
__device__ __half g_xl1h[(size_t)NMAX * 128]; // layer1 gather table (fp16)
__device__ __half g_b1h[(size_t)NMAX * 256];  // [xr1 | res1] fp16
__device__ __half g_hh[(size_t)NMAX * 128];   // layer1 output (fp16)
__device__ __half g_xl2h[(size_t)NMAX * 16];  // layer2 gather table (fp16)
__device__ __half g_b2h[(size_t)NMAX * 48];   // [xr2 | res2 | skip] fp16

__device__ __forceinline__ float ex2f(float x) {
    float r;
    asm("ex2.approx.f32 %0, %1;" : "=f"(r) : "f"(x));
    return r;
}

// ---------------- prep: transpose/cvt weights only ---------------------------
__global__ void k_prep(const float* __restrict__ Wl1, const float* __restrict__ Wr1,
                       const float* __restrict__ res1W,
                       const float* __restrict__ Wl2, const float* __restrict__ Wr2,
                       const float* __restrict__ res2W, const float* __restrict__ skipW) {
    int idx = blockIdx.x * blockDim.x + threadIdx.x;
    if (idx < 384 * 128) {
        int nn = idx >> 7, k = idx & 127;
        int seg = nn >> 7, nm = nn & 127;
        const float* W = (seg == 0) ? Wl1 : (seg == 1) ? Wr1 : res1W;
        g_w1h[nn * 128 + k] = __float2half_rn(W[k * 128 + nm]);
        return;
    }
    idx -= 384 * 128;
    if (idx < 64 * 128) {
        int nn = idx >> 7, k = idx & 127;
        int seg = nn >> 4, nm = nn & 15;
        const float* W = (seg == 0) ? Wl2 : (seg == 1) ? Wr2 : (seg == 2) ? res2W : skipW;
        g_w2h[nn * 128 + k] = __float2half_rn(W[k * 16 + nm]);
    }
}

// ---------------- bucket build ------------------------------------------------
__global__ void k_scatter(const int* __restrict__ ei, int E, int n) {
    int e = blockIdx.x * blockDim.x + threadIdx.x;
    if (e >= E + n) return;
    int s, d;
    if (e < E) { s = ei[e]; d = ei[E + e]; }
    else       { s = d = e - E; }
    int pos = atomicAdd(&g_cnt[d], 1);
    if (pos < BSTRIDE) g_colsrc[(size_t)d * BSTRIDE + pos] = s;
}

// ---------------- fp16 tensor-core GEMM (m16n8k16 + ldmatrix) ----------------
// F32A: A is fp32 in global, converted to fp16 during the smem fill.
#define LDH 136                         // smem row stride in halves (272B)
#define ASM_OFF 0
#define BSM_OFF (128 * LDH)
#define SMEM_H ((128 + 64) * LDH * 2)   // 52224 bytes

__device__ __forceinline__ void cp16(uint32_t dst, const void* src, int bytes) {
    asm volatile("cp.async.cg.shared.global [%0], [%1], 16, %2;"
                 :: "r"(dst), "l"(src), "r"(bytes));
}

__device__ __forceinline__ void ldsm4(uint32_t& r0, uint32_t& r1, uint32_t& r2,
                                      uint32_t& r3, uint32_t addr) {
    asm volatile("ldmatrix.sync.aligned.m8n8.x4.shared.b16 {%0,%1,%2,%3}, [%4];"
                 : "=r"(r0), "=r"(r1), "=r"(r2), "=r"(r3) : "r"(addr));
}

__device__ __forceinline__ void mma_f16(float c[4],
    uint32_t a0, uint32_t a1, uint32_t a2, uint32_t a3, uint32_t b0, uint32_t b1)
{
    asm volatile(
        "mma.sync.aligned.m16n8k16.row.col.f32.f16.f16.f32 "
        "{%0,%1,%2,%3}, {%4,%5,%6,%7}, {%8,%9}, {%0,%1,%2,%3};\n"
        : "+f"(c[0]), "+f"(c[1]), "+f"(c[2]), "+f"(c[3])
        : "r"(a0), "r"(a1), "r"(a2), "r"(a3), "r"(b0), "r"(b1));
}

template<bool F32A>
__global__ __launch_bounds__(256) void k_gemm_h(
    const void* __restrict__ Av, int M,
    const __half* __restrict__ Wh,
    __half* __restrict__ C0, int ldc0, int split,
    __half* __restrict__ C1, int ldc1,
    const float* __restrict__ B0, const float* __restrict__ B1,
    const float* __restrict__ B2, const float* __restrict__ B3,
    int segShift)
{
    extern __shared__ __half sm[];
    const int tid = threadIdx.x;
    const int lane = tid & 31, warp = tid >> 5;
    const int wm = warp >> 1, wn = warp & 1;
    const int warpRow = wm * 32, warpCol = wn * 32;
    const int rowBase = blockIdx.y * 128;
    const int colBase = blockIdx.x * 64;
    const int g = lane >> 2, tg = lane & 3;

    uint32_t smemBase = (uint32_t)__cvta_generic_to_shared(sm);

    // ---- B fill via cp.async (issued first, overlaps the sync A fill) ----
    #pragma unroll
    for (int l = 0; l < 4; l++) {
        int idx = tid + l * 256;
        int r = idx >> 4, c = idx & 15;
        cp16(smemBase + (BSM_OFF + r * LDH + c * 8) * 2,
             &Wh[(size_t)(colBase + r) * 128 + c * 8], 16);
    }
    asm volatile("cp.async.commit_group;");

    // ---- A fill ----
    if (F32A) {
        const float* A = (const float*)Av;
        #pragma unroll
        for (int l = 0; l < 16; l++) {
            int idx = tid + l * 256;           // 4096 float4 chunks
            int r = idx >> 5, c = idx & 31;    // 32 float4 per row
            int grow = rowBase + r;
            uint2 u = make_uint2(0u, 0u);
            if (grow < M) {
                float4 f = __ldcs((const float4*)&A[(size_t)grow * 128 + c * 4]);
                __half2 h0 = __floats2half2_rn(f.x, f.y);
                __half2 h1 = __floats2half2_rn(f.z, f.w);
                u.x = *(uint32_t*)&h0;
                u.y = *(uint32_t*)&h1;
            }
            *(uint2*)&sm[ASM_OFF + r * LDH + c * 4] = u;
        }
    } else {
        const __half* A = (const __half*)Av;
        #pragma unroll
        for (int l = 0; l < 8; l++) {
            int idx = tid + l * 256;
            int r = idx >> 4, c = idx & 15;
            int grow = rowBase + r;
            const __half* src = (grow < M) ? &A[(size_t)grow * 128 + c * 8] : A;
            cp16(smemBase + (ASM_OFF + r * LDH + c * 8) * 2, src, (grow < M) ? 16 : 0);
        }
        asm volatile("cp.async.commit_group;");
    }
    asm volatile("cp.async.wait_group 0;");
    __syncthreads();

    const int lr = (lane & 7) + ((lane >> 3) & 1) * 8;
    const int lc = (lane >> 4) * 8;

    float acc[2][4][4] = {};

    #pragma unroll
    for (int ks = 0; ks < 8; ks++) {
        int k0 = ks * 16;
        uint32_t a[2][4], bq[2][4];
        #pragma unroll
        for (int mt = 0; mt < 2; mt++) {
            uint32_t ad = smemBase +
                (ASM_OFF + (warpRow + mt * 16 + lr) * LDH + k0 + lc) * 2;
            ldsm4(a[mt][0], a[mt][1], a[mt][2], a[mt][3], ad);
        }
        #pragma unroll
        for (int ntp = 0; ntp < 2; ntp++) {
            uint32_t bd = smemBase +
                (BSM_OFF + (warpCol + ntp * 16 + lr) * LDH + k0 + lc) * 2;
            ldsm4(bq[ntp][0], bq[ntp][1], bq[ntp][2], bq[ntp][3], bd);
        }
        #pragma unroll
        for (int mt = 0; mt < 2; mt++)
            #pragma unroll
            for (int nt = 0; nt < 4; nt++)
                mma_f16(acc[mt][nt],
                        a[mt][0], a[mt][1], a[mt][2], a[mt][3],
                        bq[nt >> 1][nt & 1], bq[nt >> 1][(nt & 1) + 2]);
    }

    #pragma unroll
    for (int mt = 0; mt < 2; mt++) {
        int row0 = rowBase + warpRow + mt * 16 + g;
        #pragma unroll
        for (int nt = 0; nt < 4; nt++) {
            int gcol = colBase + warpCol + nt * 8 + 2 * tg;
            int seg = gcol >> segShift;
            int segW = 1 << segShift;
            int cm = gcol & (segW - 1);
            const float* Bv = (seg == 0) ? B0 : (seg == 1) ? B1 : (seg == 2) ? B2 : B3;
            float b0v = Bv[cm], b1v = Bv[cm + 1];
            #pragma unroll
            for (int h = 0; h < 2; h++) {
                int row = row0 + h * 8;
                if (row >= M) continue;
                __half2 hv = __floats2half2_rn(acc[mt][nt][h * 2 + 0] + b0v,
                                               acc[mt][nt][h * 2 + 1] + b1v);
                if (gcol < split) {
                    *(__half2*)&C0[(size_t)row * ldc0 + gcol] = hv;
                } else {
                    __stcs((__half2*)&C1[(size_t)row * ldc1 + gcol - split], hv);
                }
            }
        }
    }
}

// ---------------- layer-1 aggregation ----------------------------------------
__device__ __forceinline__ float4 unpack4(uint2 u) {
    float2 a = __half22float2(*(__half2*)&u.x);
    float2 b = __half22float2(*(__half2*)&u.y);
    return make_float4(a.x, a.y, b.x, b.y);
}

__device__ __forceinline__ __half2 lrelu2(__half2 e, __half2 c02) {
    return __hmax2(e, __hmul2(e, c02));
}

__global__ __launch_bounds__(64, 24) void k_agg1(
    const float* __restrict__ att1, const float* __restrict__ bias1,
    const float* __restrict__ lng, const float* __restrict__ lnb, int n)
{
    int warp = blockIdx.x * 2 + (threadIdx.x >> 5);
    int lane = threadIdx.x & 31;
    if (warp >= n) return;
    int i = warp;
    int c0 = lane * 4;

    float4 attf = *(const float4*)&att1[c0];
    __half2 att01 = __floats2half2_rn(attf.x * LOG2E, attf.y * LOG2E);
    __half2 att23 = __floats2half2_rn(attf.z * LOG2E, attf.w * LOG2E);
    const __half2 c02 = __float2half2_rn(0.2f);

    uint2 xru = __ldcs((const uint2*)&g_b1h[(size_t)i * 256 + c0]);
    __half2 xr01 = *(__half2*)&xru.x;
    __half2 xr23 = *(__half2*)&xru.y;

    int deg = min(g_cnt[i], BSTRIDE);
    const int* bucket = &g_colsrc[(size_t)i * BSTRIDE];
    const __half* tab = g_xl1h;

    float acc0 = 0.f, acc1 = 0.f, acc2 = 0.f, acc3 = 0.f, den = 0.f;

    int main4 = deg & ~3;
    for (int j = 0; j < main4; j += 4) {
        int4 cs = *(const int4*)(bucket + j);
        uint2 u0 = *(const uint2*)&tab[(size_t)cs.x * 128 + c0];
        uint2 u1 = *(const uint2*)&tab[(size_t)cs.y * 128 + c0];
        uint2 u2 = *(const uint2*)&tab[(size_t)cs.z * 128 + c0];
        uint2 u3 = *(const uint2*)&tab[(size_t)cs.w * 128 + c0];

        __half2 d0 = __hfma2(lrelu2(__hadd2(*(__half2*)&u0.x, xr01), c02), att01,
                     __hmul2(lrelu2(__hadd2(*(__half2*)&u0.y, xr23), c02), att23));
        __half2 d1 = __hfma2(lrelu2(__hadd2(*(__half2*)&u1.x, xr01), c02), att01,
                     __hmul2(lrelu2(__hadd2(*(__half2*)&u1.y, xr23), c02), att23));
        __half2 d2 = __hfma2(lrelu2(__hadd2(*(__half2*)&u2.x, xr01), c02), att01,
                     __hmul2(lrelu2(__hadd2(*(__half2*)&u2.y, xr23), c02), att23));
        __half2 d3 = __hfma2(lrelu2(__hadd2(*(__half2*)&u3.x, xr01), c02), att01,
                     __hmul2(lrelu2(__hadd2(*(__half2*)&u3.y, xr23), c02), att23));

        float p0 = __half2float(__hadd(__low2half(d0), __high2half(d0)));
        float p1 = __half2float(__hadd(__low2half(d1), __high2half(d1)));
        float p2 = __half2float(__hadd(__low2half(d2), __high2half(d2)));
        float p3 = __half2float(__hadd(__low2half(d3), __high2half(d3)));

        p0 += __shfl_xor_sync(0xffffffffu, p0, 1);
        p1 += __shfl_xor_sync(0xffffffffu, p1, 1);
        p2 += __shfl_xor_sync(0xffffffffu, p2, 1);
        p3 += __shfl_xor_sync(0xffffffffu, p3, 1);
        p0 += __shfl_xor_sync(0xffffffffu, p0, 2);
        p1 += __shfl_xor_sync(0xffffffffu, p1, 2);
        p2 += __shfl_xor_sync(0xffffffffu, p2, 2);
        p3 += __shfl_xor_sync(0xffffffffu, p3, 2);

        float w0 = ex2f(p0);
        float w1 = ex2f(p1);
        float w2 = ex2f(p2);
        float w3 = ex2f(p3);

        __half2 w0h = __float2half2_rn(w0);
        __half2 w1h = __float2half2_rn(w1);
        __half2 w2h = __float2half2_rn(w2);
        __half2 w3h = __float2half2_rn(w3);

        __half2 g01 = __hmul2(*(__half2*)&u0.x, w0h);
        g01 = __hfma2(*(__half2*)&u1.x, w1h, g01);
        g01 = __hfma2(*(__half2*)&u2.x, w2h, g01);
        g01 = __hfma2(*(__half2*)&u3.x, w3h, g01);
        __half2 g23 = __hmul2(*(__half2*)&u0.y, w0h);
        g23 = __hfma2(*(__half2*)&u1.y, w1h, g23);
        g23 = __hfma2(*(__half2*)&u2.y, w2h, g23);
        g23 = __hfma2(*(__half2*)&u3.y, w3h, g23);

        float2 f01 = __half22float2(g01);
        float2 f23 = __half22float2(g23);
        acc0 += f01.x; acc1 += f01.y;
        acc2 += f23.x; acc3 += f23.y;
        den += (w0 + w1) + (w2 + w3);
    }
    for (int j = main4; j < deg; j++) {
        int s = bucket[j];
        uint2 u0 = *(const uint2*)&tab[(size_t)s * 128 + c0];
        __half2 d0 = __hfma2(lrelu2(__hadd2(*(__half2*)&u0.x, xr01), c02), att01,
                     __hmul2(lrelu2(__hadd2(*(__half2*)&u0.y, xr23), c02), att23));
        float p = __half2float(__hadd(__low2half(d0), __high2half(d0)));
        p += __shfl_xor_sync(0xffffffffu, p, 1);
        p += __shfl_xor_sync(0xffffffffu, p, 2);
        float w = ex2f(p);
        float4 x0 = unpack4(u0);
        acc0 += x0.x * w;
        acc1 += x0.y * w;
        acc2 += x0.z * w;
        acc3 += x0.w * w;
        den += w;
    }

    float inv = 1.f / den;
    float4 bia = *(const float4*)&bias1[c0];
    float v0 = acc0 * inv + bia.x;
    float v1 = acc1 * inv + bia.y;
    float v2 = acc2 * inv + bia.z;
    float v3 = acc3 * inv + bia.w;

    float s1 = v0 + v1 + v2 + v3;
    float s2 = v0 * v0 + v1 * v1 + v2 * v2 + v3 * v3;
    #pragma unroll
    for (int o = 16; o >= 1; o >>= 1) {
        s1 += __shfl_xor_sync(0xffffffffu, s1, o);
        s2 += __shfl_xor_sync(0xffffffffu, s2, o);
    }
    float mu = s1 * (1.f / 128.f);
    float var = fmaxf(s2 * (1.f / 128.f) - mu * mu, 0.f);
    float rstd = rsqrtf(var + 1e-5f);

    float4 gg = *(const float4*)&lng[c0];
    float4 bb = *(const float4*)&lnb[c0];
    float4 rs = unpack4(__ldcs((const uint2*)&g_b1h[(size_t)i * 256 + 128 + c0]));
    float y0 = (v0 - mu) * rstd * gg.x + bb.x + rs.x;
    float y1 = (v1 - mu) * rstd * gg.y + bb.y + rs.y;
    float y2 = (v2 - mu) * rstd * gg.z + bb.z + rs.z;
    float y3 = (v3 - mu) * rstd * gg.w + bb.w + rs.w;
    y0 = y0 > 0.f ? y0 : ex2f(y0 * LOG2E) - 1.f;
    y1 = y1 > 0.f ? y1 : ex2f(y1 * LOG2E) - 1.f;
    y2 = y2 > 0.f ? y2 : ex2f(y2 * LOG2E) - 1.f;
    y3 = y3 > 0.f ? y3 : ex2f(y3 * LOG2E) - 1.f;

    __half2 h01 = __floats2half2_rn(y0, y1);
    __half2 h23 = __floats2half2_rn(y2, y3);
    uint2 up;
    up.x = *(uint32_t*)&h01;
    up.y = *(uint32_t*)&h23;
    __stcs((uint2*)&g_hh[(size_t)i * 128 + c0], up);
}

// ------ layer-2 aggregation: 4 edge slots x 8 lanes x 2 channels -------------
__global__ __launch_bounds__(64, 24) void k_agg2(
    const float* __restrict__ att2, const float* __restrict__ bias2,
    const float* __restrict__ lng, const float* __restrict__ lnb,
    const float* __restrict__ outW, const float* __restrict__ outb,
    float* __restrict__ out, int n)
{
    int warp = blockIdx.x * 2 + (threadIdx.x >> 5);
    int lane = threadIdx.x & 31;
    if (warp >= n) return;
    int i = warp;
    int c2 = (lane & 7) * 2;   // channel pair
    int sub = lane >> 3;       // edge slot (4 per iteration)

    __half2 xr2 = *(const __half2*)&g_b2h[(size_t)i * 48 + c2];
    float2 attf = *(const float2*)&att2[c2];
    __half2 attc2 = __floats2half2_rn(attf.x * LOG2E, attf.y * LOG2E);
    const __half2 c02 = __float2half2_rn(0.2f);

    int deg = min(g_cnt[i], BSTRIDE);
    const int* bucket = &g_colsrc[(size_t)i * BSTRIDE];
    float a0 = 0.f, a1 = 0.f, den = 0.f;

    for (int j0 = 0; j0 < deg; j0 += 4) {
        int j = j0 + sub;
        bool valid = (j < deg);
        int s = bucket[valid ? j : 0];
        __half2 xs2 = *(const __half2*)&g_xl2h[(size_t)s * 16 + c2];
        __half2 t2 = __hmul2(lrelu2(__hadd2(xs2, xr2), c02), attc2);
        float p = __half2float(__hadd(__low2half(t2), __high2half(t2)));
        p += __shfl_xor_sync(0xffffffffu, p, 1);
        p += __shfl_xor_sync(0xffffffffu, p, 2);
        p += __shfl_xor_sync(0xffffffffu, p, 4);
        float w = valid ? ex2f(p) : 0.f;
        float2 xf = __half22float2(xs2);
        a0 += xf.x * w;
        a1 += xf.y * w;
        den += w;
    }
    a0 += __shfl_xor_sync(0xffffffffu, a0, 8);
    a1 += __shfl_xor_sync(0xffffffffu, a1, 8);
    den += __shfl_xor_sync(0xffffffffu, den, 8);
    a0 += __shfl_xor_sync(0xffffffffu, a0, 16);
    a1 += __shfl_xor_sync(0xffffffffu, a1, 16);
    den += __shfl_xor_sync(0xffffffffu, den, 16);

    float inv = 1.f / den;
    float2 b2 = *(const float2*)&bias2[c2];
    float v0 = a0 * inv + b2.x;
    float v1 = a1 * inv + b2.y;

    float s1 = v0 + v1, s2 = v0 * v0 + v1 * v1;
    #pragma unroll
    for (int o = 4; o >= 1; o >>= 1) {
        s1 += __shfl_xor_sync(0xffffffffu, s1, o);
        s2 += __shfl_xor_sync(0xffffffffu, s2, o);
    }
    float mu = s1 * (1.f / 16.f);
    float var = fmaxf(s2 * (1.f / 16.f) - mu * mu, 0.f);
    float rstd = rsqrtf(var + 1e-5f);

    float2 gg = *(const float2*)&lng[c2];
    float2 bb = *(const float2*)&lnb[c2];
    float2 rf = __half22float2(*(const __half2*)&g_b2h[(size_t)i * 48 + 16 + c2]);
    float y0 = (v0 - mu) * rstd * gg.x + bb.x + rf.x;
    float y1 = (v1 - mu) * rstd * gg.y + bb.y + rf.y;
    y0 = y0 > 0.f ? y0 : ex2f(y0 * LOG2E) - 1.f;
    y1 = y1 > 0.f ? y1 : ex2f(y1 * LOG2E) - 1.f;
    float2 sf = __half22float2(*(const __half2*)&g_b2h[(size_t)i * 48 + 32 + c2]);
    y0 += sf.x;
    y1 += sf.y;

    float o0 = __ldg(&outb[lane * 2 + 0]);
    float o1 = __ldg(&outb[lane * 2 + 1]);
    #pragma unroll
    for (int cc = 0; cc < 16; cc++) {
        float hv = (cc & 1) ? __shfl_sync(0xffffffffu, y1, cc >> 1)
                            : __shfl_sync(0xffffffffu, y0, cc >> 1);
        float2 w2 = __ldg((const float2*)&outW[cc * 64 + lane * 2]);
        o0 += hv * w2.x;
        o1 += hv * w2.y;
    }
    *(float2*)&out[(size_t)i * 64 + lane * 2] = make_float2(o0, o1);
}

// ---------------------------------------------------------------------------
extern "C" void kernel_launch(void* const* d_in, const int* in_sizes, int n_in,
                              void* d_out, int out_size) {
    const float* x    = (const float*)d_in[0];
    const int*   ei   = (const int*)d_in[1];
    const float* Wl1  = (const float*)d_in[2];
    const float* bl1  = (const float*)d_in[3];
    const float* Wr1  = (const float*)d_in[4];
    const float* br1  = (const float*)d_in[5];
    const float* att1 = (const float*)d_in[6];
    const float* bias1= (const float*)d_in[7];
    const float* Wl2  = (const float*)d_in[8];
    const float* bl2  = (const float*)d_in[9];
    const float* Wr2  = (const float*)d_in[10];
    const float* br2  = (const float*)d_in[11];
    const float* att2 = (const float*)d_in[12];
    const float* bias2= (const float*)d_in[13];
    const float* ln1g = (const float*)d_in[14];
    const float* ln1b = (const float*)d_in[15];
    const float* ln2g = (const float*)d_in[16];
    const float* ln2b = (const float*)d_in[17];
    const float* res1W= (const float*)d_in[18];
    const float* res1b= (const float*)d_in[19];
    const float* res2W= (const float*)d_in[20];
    const float* res2b= (const float*)d_in[21];
    const float* skipW= (const float*)d_in[22];
    const float* skipb= (const float*)d_in[23];
    const float* outW = (const float*)d_in[24];
    const float* outb = (const float*)d_in[25];
    float* out = (float*)d_out;

    int n = in_sizes[0] / FIN;
    int E = in_sizes[1] / 2;

    void *w1h, *w2h, *xl1h, *b1h, *hh, *xl2h, *b2h;
    int* cnt;
    cudaGetSymbolAddress(&w1h, g_w1h);
    cudaGetSymbolAddress(&w2h, g_w2h);
    cudaGetSymbolAddress(&xl1h, g_xl1h);
    cudaGetSymbolAddress(&b1h, g_b1h);
    cudaGetSymbolAddress(&hh, g_hh);
    cudaGetSymbolAddress(&xl2h, g_xl2h);
    cudaGetSymbolAddress(&b2h, g_b2h);
    cudaGetSymbolAddress((void**)&cnt, g_cnt);

    static bool attr_set = false;
    if (!attr_set) {
        cudaFuncSetAttribute(k_gemm_h<true>,
            cudaFuncAttributeMaxDynamicSharedMemorySize, SMEM_H);
        cudaFuncSetAttribute(k_gemm_h<false>,
            cudaFuncAttributeMaxDynamicSharedMemorySize, SMEM_H);
        attr_set = true;
    }

    cudaMemsetAsync(cnt, 0, (size_t)n * sizeof(int));
    k_scatter<<<(E + n + 255) / 256, 256>>>(ei, E, n);

    int prepTotal = 384 * 128 + 64 * 128;
    k_prep<<<(prepTotal + 255) / 256, 256>>>(Wl1, Wr1, res1W,
                                             Wl2, Wr2, res2W, skipW);

    int nb128 = (n + 127) / 128;

    // GEMM1 (A fp32 direct): x[n,128] @ W1h -> xl1h [n,128] fp16, b1h [n,256] fp16
    k_gemm_h<true><<<dim3(6, nb128), 256, SMEM_H>>>(
        x, n, (const __half*)w1h,
        (__half*)xl1h, 128, 128, (__half*)b1h, 256,
        bl1, br1, res1b, res1b, 7);

    k_agg1<<<(n + 1) / 2, 64>>>(att1, bias1, ln1g, ln1b, n);

    // GEMM2 (A fp16): hh[n,128] @ W2h -> xl2h [n,16] fp16, b2h [n,48] fp16
    k_gemm_h<false><<<dim3(1, nb128), 256, SMEM_H>>>(
        hh, n, (const __half*)w2h,
        (__half*)xl2h, 16, 16, (__half*)b2h, 48,
        bl2, br2, res2b, skipb, 4);

    k_agg2<<<(n + 1) / 2, 64>>>(att2, bias2, ln2g, ln2b, outW, outb, out, n);
}

// round 17
// speedup vs baseline: 1.0180x; 1.0180x over previous
#include <cuda_runtime.h>
#include <cuda_fp16.h>
#include <math.h>
#include <stdint.h>

#define NMAX 100000
#define EMAX 1600000
#define FIN 128
#define BSTRIDE 64          // bucket stride (max degree supported)
#define LOG2E 1.4426950408889634f

// ---------------- scratch (static device memory; no allocations) -------------
__device__ int    g_cnt[NMAX];
__device__ int    g_colsrc[(size_t)NMAX * BSTRIDE];
__device__ __half g_xh[(size_t)NMAX * 128];   // x in fp16
__device__ __half g_w1h[384 * 128];           // [n][k] fp16: Wl1|Wr1|res1W
__device__ __half g_w2h[64 * 128];            // [n][k] fp16: Wl2|Wr2|res2W|skipW
__device__ __half g_xl1h[(size_t)NMAX * 128]; // layer1 gather table (fp16)
__device__ __half g_b1h[(size_t)NMAX * 256];  // [xr1 | res1] fp16
__device__ __half g_hh[(size_t)NMAX * 128];   // layer1 output (fp16)
__device__ __half g_xl2h[(size_t)NMAX * 16];  // layer2 gather table (fp16)
__device__ __half g_b2h[(size_t)NMAX * 48];   // [xr2 | res2 | skip] fp16

__device__ __forceinline__ float ex2f(float x) {
    float r;
    asm("ex2.approx.f32 %0, %1;" : "=f"(r) : "f"(x));
    return r;
}

// ------- fused prep: cvt x + transpose/cvt weights + zero cnt ---------------
__global__ void k_prep(const float* __restrict__ x, int total4, int n,
                       const float* __restrict__ Wl1, const float* __restrict__ Wr1,
                       const float* __restrict__ res1W,
                       const float* __restrict__ Wl2, const float* __restrict__ Wr2,
                       const float* __restrict__ res2W, const float* __restrict__ skipW) {
    int i = blockIdx.x * blockDim.x + threadIdx.x;
    if (i < total4) {
        float4 f = ((const float4*)x)[i];
        __half2 h0 = __floats2half2_rn(f.x, f.y);
        __half2 h1 = __floats2half2_rn(f.z, f.w);
        uint2 u;
        u.x = *(uint32_t*)&h0;
        u.y = *(uint32_t*)&h1;
        ((uint2*)g_xh)[i] = u;
        return;
    }
    int idx = i - total4;
    if (idx < 384 * 128) {
        int nn = idx >> 7, k = idx & 127;
        int seg = nn >> 7, nm = nn & 127;
        const float* W = (seg == 0) ? Wl1 : (seg == 1) ? Wr1 : res1W;
        g_w1h[nn * 128 + k] = __float2half_rn(W[k * 128 + nm]);
        return;
    }
    idx -= 384 * 128;
    if (idx < 64 * 128) {
        int nn = idx >> 7, k = idx & 127;
        int seg = nn >> 4, nm = nn & 15;
        const float* W = (seg == 0) ? Wl2 : (seg == 1) ? Wr2 : (seg == 2) ? res2W : skipW;
        g_w2h[nn * 128 + k] = __float2half_rn(W[k * 16 + nm]);
        return;
    }
    idx -= 64 * 128;
    if (idx < n) g_cnt[idx] = 0;
}

// ---------------- bucket build ------------------------------------------------
__global__ void k_scatter(const int* __restrict__ ei, int E, int n) {
    int e = blockIdx.x * blockDim.x + threadIdx.x;
    if (e >= E + n) return;
    int s, d;
    if (e < E) { s = ei[e]; d = ei[E + e]; }
    else       { s = d = e - E; }
    int pos = atomicAdd(&g_cnt[d], 1);
    if (pos < BSTRIDE) g_colsrc[(size_t)d * BSTRIDE + pos] = s;
}

// ---------------- fp16 tensor-core GEMM (m16n8k16 + ldmatrix) ----------------
#define LDH 136                         // smem row stride in halves (272B)
#define ASM_OFF 0
#define BSM_OFF (128 * LDH)
#define SMEM_H ((128 + 64) * LDH * 2)   // 52224 bytes

__device__ __forceinline__ void cp16(uint32_t dst, const void* src, int bytes) {
    asm volatile("cp.async.cg.shared.global [%0], [%1], 16, %2;"
                 :: "r"(dst), "l"(src), "r"(bytes));
}

__device__ __forceinline__ void ldsm4(uint32_t& r0, uint32_t& r1, uint32_t& r2,
                                      uint32_t& r3, uint32_t addr) {
    asm volatile("ldmatrix.sync.aligned.m8n8.x4.shared.b16 {%0,%1,%2,%3}, [%4];"
                 : "=r"(r0), "=r"(r1), "=r"(r2), "=r"(r3) : "r"(addr));
}

__device__ __forceinline__ void mma_f16(float c[4],
    uint32_t a0, uint32_t a1, uint32_t a2, uint32_t a3, uint32_t b0, uint32_t b1)
{
    asm volatile(
        "mma.sync.aligned.m16n8k16.row.col.f32.f16.f16.f32 "
        "{%0,%1,%2,%3}, {%4,%5,%6,%7}, {%8,%9}, {%0,%1,%2,%3};\n"
        : "+f"(c[0]), "+f"(c[1]), "+f"(c[2]), "+f"(c[3])
        : "r"(a0), "r"(a1), "r"(a2), "r"(a3), "r"(b0), "r"(b1));
}

__global__ __launch_bounds__(256) void k_gemm_h(
    const __half* __restrict__ A, int M,
    const __half* __restrict__ Wh,
    __half* __restrict__ C0, int ldc0, int split,
    __half* __restrict__ C1, int ldc1,
    const float* __restrict__ B0, const float* __restrict__ B1,
    const float* __restrict__ B2, const float* __restrict__ B3,
    int segShift)
{
    extern __shared__ __half sm[];
    const int tid = threadIdx.x;
    const int lane = tid & 31, warp = tid >> 5;
    const int wm = warp >> 1, wn = warp & 1;
    const int warpRow = wm * 32, warpCol = wn * 32;
    const int rowBase = blockIdx.y * 128;
    const int colBase = blockIdx.x * 64;
    const int g = lane >> 2, tg = lane & 3;

    uint32_t smemBase = (uint32_t)__cvta_generic_to_shared(sm);

    #pragma unroll
    for (int l = 0; l < 8; l++) {
        int idx = tid + l * 256;
        int r = idx >> 4, c = idx & 15;
        int grow = rowBase + r;
        const __half* src = (grow < M) ? &A[(size_t)grow * 128 + c * 8] : A;
        cp16(smemBase + (ASM_OFF + r * LDH + c * 8) * 2, src, (grow < M) ? 16 : 0);
    }
    #pragma unroll
    for (int l = 0; l < 4; l++) {
        int idx = tid + l * 256;
        int r = idx >> 4, c = idx & 15;
        cp16(smemBase + (BSM_OFF + r * LDH + c * 8) * 2,
             &Wh[(size_t)(colBase + r) * 128 + c * 8], 16);
    }
    asm volatile("cp.async.commit_group;");
    asm volatile("cp.async.wait_group 0;");
    __syncthreads();

    const int lr = (lane & 7) + ((lane >> 3) & 1) * 8;
    const int lc = (lane >> 4) * 8;

    float acc[2][4][4] = {};

    #pragma unroll
    for (int ks = 0; ks < 8; ks++) {
        int k0 = ks * 16;
        uint32_t a[2][4], bq[2][4];
        #pragma unroll
        for (int mt = 0; mt < 2; mt++) {
            uint32_t ad = smemBase +
                (ASM_OFF + (warpRow + mt * 16 + lr) * LDH + k0 + lc) * 2;
            ldsm4(a[mt][0], a[mt][1], a[mt][2], a[mt][3], ad);
        }
        #pragma unroll
        for (int ntp = 0; ntp < 2; ntp++) {
            uint32_t bd = smemBase +
                (BSM_OFF + (warpCol + ntp * 16 + lr) * LDH + k0 + lc) * 2;
            ldsm4(bq[ntp][0], bq[ntp][1], bq[ntp][2], bq[ntp][3], bd);
        }
        #pragma unroll
        for (int mt = 0; mt < 2; mt++)
            #pragma unroll
            for (int nt = 0; nt < 4; nt++)
                mma_f16(acc[mt][nt],
                        a[mt][0], a[mt][1], a[mt][2], a[mt][3],
                        bq[nt >> 1][nt & 1], bq[nt >> 1][(nt & 1) + 2]);
    }

    #pragma unroll
    for (int mt = 0; mt < 2; mt++) {
        int row0 = rowBase + warpRow + mt * 16 + g;
        #pragma unroll
        for (int nt = 0; nt < 4; nt++) {
            int gcol = colBase + warpCol + nt * 8 + 2 * tg;
            int seg = gcol >> segShift;
            int segW = 1 << segShift;
            int cm = gcol & (segW - 1);
            const float* Bv = (seg == 0) ? B0 : (seg == 1) ? B1 : (seg == 2) ? B2 : B3;
            float b0v = Bv[cm], b1v = Bv[cm + 1];
            #pragma unroll
            for (int h = 0; h < 2; h++) {
                int row = row0 + h * 8;
                if (row >= M) continue;
                __half2 hv = __floats2half2_rn(acc[mt][nt][h * 2 + 0] + b0v,
                                               acc[mt][nt][h * 2 + 1] + b1v);
                if (gcol < split) {
                    *(__half2*)&C0[(size_t)row * ldc0 + gcol] = hv;
                } else {
                    __stcs((__half2*)&C1[(size_t)row * ldc1 + gcol - split], hv);
                }
            }
        }
    }
}

// ---------------- layer-1 aggregation ----------------------------------------
__device__ __forceinline__ float4 unpack4(uint2 u) {
    float2 a = __half22float2(*(__half2*)&u.x);
    float2 b = __half22float2(*(__half2*)&u.y);
    return make_float4(a.x, a.y, b.x, b.y);
}

__device__ __forceinline__ __half2 lrelu2(__half2 e, __half2 c02) {
    return __hmax2(e, __hmul2(e, c02));
}

__global__ __launch_bounds__(64, 24) void k_agg1(
    const float* __restrict__ att1, const float* __restrict__ bias1,
    const float* __restrict__ lng, const float* __restrict__ lnb, int n)
{
    int warp = blockIdx.x * 2 + (threadIdx.x >> 5);
    int lane = threadIdx.x & 31;
    if (warp >= n) return;
    int i = warp;
    int c0 = lane * 4;

    float4 attf = *(const float4*)&att1[c0];
    __half2 att01 = __floats2half2_rn(attf.x * LOG2E, attf.y * LOG2E);
    __half2 att23 = __floats2half2_rn(attf.z * LOG2E, attf.w * LOG2E);
    const __half2 c02 = __float2half2_rn(0.2f);

    uint2 xru = __ldcs((const uint2*)&g_b1h[(size_t)i * 256 + c0]);
    __half2 xr01 = *(__half2*)&xru.x;
    __half2 xr23 = *(__half2*)&xru.y;

    int deg = min(g_cnt[i], BSTRIDE);
    const int* bucket = &g_colsrc[(size_t)i * BSTRIDE];
    const __half* tab = g_xl1h;

    float acc0 = 0.f, acc1 = 0.f, acc2 = 0.f, acc3 = 0.f, den = 0.f;

    int main4 = deg & ~3;
    for (int j = 0; j < main4; j += 4) {
        int4 cs = *(const int4*)(bucket + j);
        uint2 u0 = *(const uint2*)&tab[(size_t)cs.x * 128 + c0];
        uint2 u1 = *(const uint2*)&tab[(size_t)cs.y * 128 + c0];
        uint2 u2 = *(const uint2*)&tab[(size_t)cs.z * 128 + c0];
        uint2 u3 = *(const uint2*)&tab[(size_t)cs.w * 128 + c0];

        __half2 d0 = __hfma2(lrelu2(__hadd2(*(__half2*)&u0.x, xr01), c02), att01,
                     __hmul2(lrelu2(__hadd2(*(__half2*)&u0.y, xr23), c02), att23));
        __half2 d1 = __hfma2(lrelu2(__hadd2(*(__half2*)&u1.x, xr01), c02), att01,
                     __hmul2(lrelu2(__hadd2(*(__half2*)&u1.y, xr23), c02), att23));
        __half2 d2 = __hfma2(lrelu2(__hadd2(*(__half2*)&u2.x, xr01), c02), att01,
                     __hmul2(lrelu2(__hadd2(*(__half2*)&u2.y, xr23), c02), att23));
        __half2 d3 = __hfma2(lrelu2(__hadd2(*(__half2*)&u3.x, xr01), c02), att01,
                     __hmul2(lrelu2(__hadd2(*(__half2*)&u3.y, xr23), c02), att23));

        float p0 = __half2float(__hadd(__low2half(d0), __high2half(d0)));
        float p1 = __half2float(__hadd(__low2half(d1), __high2half(d1)));
        float p2 = __half2float(__hadd(__low2half(d2), __high2half(d2)));
        float p3 = __half2float(__hadd(__low2half(d3), __high2half(d3)));

        p0 += __shfl_xor_sync(0xffffffffu, p0, 1);
        p1 += __shfl_xor_sync(0xffffffffu, p1, 1);
        p2 += __shfl_xor_sync(0xffffffffu, p2, 1);
        p3 += __shfl_xor_sync(0xffffffffu, p3, 1);
        p0 += __shfl_xor_sync(0xffffffffu, p0, 2);
        p1 += __shfl_xor_sync(0xffffffffu, p1, 2);
        p2 += __shfl_xor_sync(0xffffffffu, p2, 2);
        p3 += __shfl_xor_sync(0xffffffffu, p3, 2);

        float w0 = ex2f(p0);
        float w1 = ex2f(p1);
        float w2 = ex2f(p2);
        float w3 = ex2f(p3);

        __half2 w0h = __float2half2_rn(w0);
        __half2 w1h = __float2half2_rn(w1);
        __half2 w2h = __float2half2_rn(w2);
        __half2 w3h = __float2half2_rn(w3);

        __half2 g01 = __hmul2(*(__half2*)&u0.x, w0h);
        g01 = __hfma2(*(__half2*)&u1.x, w1h, g01);
        g01 = __hfma2(*(__half2*)&u2.x, w2h, g01);
        g01 = __hfma2(*(__half2*)&u3.x, w3h, g01);
        __half2 g23 = __hmul2(*(__half2*)&u0.y, w0h);
        g23 = __hfma2(*(__half2*)&u1.y, w1h, g23);
        g23 = __hfma2(*(__half2*)&u2.y, w2h, g23);
        g23 = __hfma2(*(__half2*)&u3.y, w3h, g23);

        float2 f01 = __half22float2(g01);
        float2 f23 = __half22float2(g23);
        acc0 += f01.x; acc1 += f01.y;
        acc2 += f23.x; acc3 += f23.y;
        den += (w0 + w1) + (w2 + w3);
    }
    for (int j = main4; j < deg; j++) {
        int s = bucket[j];
        uint2 u0 = *(const uint2*)&tab[(size_t)s * 128 + c0];
        __half2 d0 = __hfma2(lrelu2(__hadd2(*(__half2*)&u0.x, xr01), c02), att01,
                     __hmul2(lrelu2(__hadd2(*(__half2*)&u0.y, xr23), c02), att23));
        float p = __half2float(__hadd(__low2half(d0), __high2half(d0)));
        p += __shfl_xor_sync(0xffffffffu, p, 1);
        p += __shfl_xor_sync(0xffffffffu, p, 2);
        float w = ex2f(p);
        float4 x0 = unpack4(u0);
        acc0 += x0.x * w;
        acc1 += x0.y * w;
        acc2 += x0.z * w;
        acc3 += x0.w * w;
        den += w;
    }

    float inv = 1.f / den;
    float4 bia = *(const float4*)&bias1[c0];
    float v0 = acc0 * inv + bia.x;
    float v1 = acc1 * inv + bia.y;
    float v2 = acc2 * inv + bia.z;
    float v3 = acc3 * inv + bia.w;

    float s1 = v0 + v1 + v2 + v3;
    float s2 = v0 * v0 + v1 * v1 + v2 * v2 + v3 * v3;
    #pragma unroll
    for (int o = 16; o >= 1; o >>= 1) {
        s1 += __shfl_xor_sync(0xffffffffu, s1, o);
        s2 += __shfl_xor_sync(0xffffffffu, s2, o);
    }
    float mu = s1 * (1.f / 128.f);
    float var = fmaxf(s2 * (1.f / 128.f) - mu * mu, 0.f);
    float rstd = rsqrtf(var + 1e-5f);

    float4 gg = *(const float4*)&lng[c0];
    float4 bb = *(const float4*)&lnb[c0];
    float4 rs = unpack4(__ldcs((const uint2*)&g_b1h[(size_t)i * 256 + 128 + c0]));
    float y0 = (v0 - mu) * rstd * gg.x + bb.x + rs.x;
    float y1 = (v1 - mu) * rstd * gg.y + bb.y + rs.y;
    float y2 = (v2 - mu) * rstd * gg.z + bb.z + rs.z;
    float y3 = (v3 - mu) * rstd * gg.w + bb.w + rs.w;
    y0 = y0 > 0.f ? y0 : ex2f(y0 * LOG2E) - 1.f;
    y1 = y1 > 0.f ? y1 : ex2f(y1 * LOG2E) - 1.f;
    y2 = y2 > 0.f ? y2 : ex2f(y2 * LOG2E) - 1.f;
    y3 = y3 > 0.f ? y3 : ex2f(y3 * LOG2E) - 1.f;

    __half2 h01 = __floats2half2_rn(y0, y1);
    __half2 h23 = __floats2half2_rn(y2, y3);
    uint2 up;
    up.x = *(uint32_t*)&h01;
    up.y = *(uint32_t*)&h23;
    __stcs((uint2*)&g_hh[(size_t)i * 128 + c0], up);
}

// ------ layer-2 aggregation: 4 edge slots x 8 lanes x 2 channels -------------
__global__ __launch_bounds__(64, 24) void k_agg2(
    const float* __restrict__ att2, const float* __restrict__ bias2,
    const float* __restrict__ lng, const float* __restrict__ lnb,
    const float* __restrict__ outW, const float* __restrict__ outb,
    float* __restrict__ out, int n)
{
    int warp = blockIdx.x * 2 + (threadIdx.x >> 5);
    int lane = threadIdx.x & 31;
    if (warp >= n) return;
    int i = warp;
    int c2 = (lane & 7) * 2;   // channel pair
    int sub = lane >> 3;       // edge slot (4 per iteration)

    __half2 xr2 = *(const __half2*)&g_b2h[(size_t)i * 48 + c2];
    float2 attf = *(const float2*)&att2[c2];
    __half2 attc2 = __floats2half2_rn(attf.x * LOG2E, attf.y * LOG2E);
    const __half2 c02 = __float2half2_rn(0.2f);

    int deg = min(g_cnt[i], BSTRIDE);
    const int* bucket = &g_colsrc[(size_t)i * BSTRIDE];
    float a0 = 0.f, a1 = 0.f, den = 0.f;

    for (int j0 = 0; j0 < deg; j0 += 4) {
        int j = j0 + sub;
        bool valid = (j < deg);
        int s = bucket[valid ? j : 0];
        __half2 xs2 = *(const __half2*)&g_xl2h[(size_t)s * 16 + c2];
        __half2 t2 = __hmul2(lrelu2(__hadd2(xs2, xr2), c02), attc2);
        float p = __half2float(__hadd(__low2half(t2), __high2half(t2)));
        p += __shfl_xor_sync(0xffffffffu, p, 1);
        p += __shfl_xor_sync(0xffffffffu, p, 2);
        p += __shfl_xor_sync(0xffffffffu, p, 4);
        float w = valid ? ex2f(p) : 0.f;
        float2 xf = __half22float2(xs2);
        a0 += xf.x * w;
        a1 += xf.y * w;
        den += w;
    }
    a0 += __shfl_xor_sync(0xffffffffu, a0, 8);
    a1 += __shfl_xor_sync(0xffffffffu, a1, 8);
    den += __shfl_xor_sync(0xffffffffu, den, 8);
    a0 += __shfl_xor_sync(0xffffffffu, a0, 16);
    a1 += __shfl_xor_sync(0xffffffffu, a1, 16);
    den += __shfl_xor_sync(0xffffffffu, den, 16);

    float inv = 1.f / den;
    float2 b2 = *(const float2*)&bias2[c2];
    float v0 = a0 * inv + b2.x;
    float v1 = a1 * inv + b2.y;

    float s1 = v0 + v1, s2 = v0 * v0 + v1 * v1;
    #pragma unroll
    for (int o = 4; o >= 1; o >>= 1) {
        s1 += __shfl_xor_sync(0xffffffffu, s1, o);
        s2 += __shfl_xor_sync(0xffffffffu, s2, o);
    }
    float mu = s1 * (1.f / 16.f);
    float var = fmaxf(s2 * (1.f / 16.f) - mu * mu, 0.f);
    float rstd = rsqrtf(var + 1e-5f);

    float2 gg = *(const float2*)&lng[c2];
    float2 bb = *(const float2*)&lnb[c2];
    float2 rf = __half22float2(*(const __half2*)&g_b2h[(size_t)i * 48 + 16 + c2]);
    float y0 = (v0 - mu) * rstd * gg.x + bb.x + rf.x;
    float y1 = (v1 - mu) * rstd * gg.y + bb.y + rf.y;
    y0 = y0 > 0.f ? y0 : ex2f(y0 * LOG2E) - 1.f;
    y1 = y1 > 0.f ? y1 : ex2f(y1 * LOG2E) - 1.f;
    float2 sf = __half22float2(*(const __half2*)&g_b2h[(size_t)i * 48 + 32 + c2]);
    y0 += sf.x;
    y1 += sf.y;

    float o0 = __ldg(&outb[lane * 2 + 0]);
    float o1 = __ldg(&outb[lane * 2 + 1]);
    #pragma unroll
    for (int cc = 0; cc < 16; cc++) {
        float hv = (cc & 1) ? __shfl_sync(0xffffffffu, y1, cc >> 1)
                            : __shfl_sync(0xffffffffu, y0, cc >> 1);
        float2 w2 = __ldg((const float2*)&outW[cc * 64 + lane * 2]);
        o0 += hv * w2.x;
        o1 += hv * w2.y;
    }
    *(float2*)&out[(size_t)i * 64 + lane * 2] = make_float2(o0, o1);
}

// ---------------------------------------------------------------------------
extern "C" void kernel_launch(void* const* d_in, const int* in_sizes, int n_in,
                              void* d_out, int out_size) {
    const float* x    = (const float*)d_in[0];
    const int*   ei   = (const int*)d_in[1];
    const float* Wl1  = (const float*)d_in[2];
    const float* bl1  = (const float*)d_in[3];
    const float* Wr1  = (const float*)d_in[4];
    const float* br1  = (const float*)d_in[5];
    const float* att1 = (const float*)d_in[6];
    const float* bias1= (const float*)d_in[7];
    const float* Wl2  = (const float*)d_in[8];
    const float* bl2  = (const float*)d_in[9];
    const float* Wr2  = (const float*)d_in[10];
    const float* br2  = (const float*)d_in[11];
    const float* att2 = (const float*)d_in[12];
    const float* bias2= (const float*)d_in[13];
    const float* ln1g = (const float*)d_in[14];
    const float* ln1b = (const float*)d_in[15];
    const float* ln2g = (const float*)d_in[16];
    const float* ln2b = (const float*)d_in[17];
    const float* res1W= (const float*)d_in[18];
    const float* res1b= (const float*)d_in[19];
    const float* res2W= (const float*)d_in[20];
    const float* res2b= (const float*)d_in[21];
    const float* skipW= (const float*)d_in[22];
    const float* skipb= (const float*)d_in[23];
    const float* outW = (const float*)d_in[24];
    const float* outb = (const float*)d_in[25];
    float* out = (float*)d_out;

    int n = in_sizes[0] / FIN;
    int E = in_sizes[1] / 2;

    void *xh, *w1h, *w2h, *xl1h, *b1h, *hh, *xl2h, *b2h;
    cudaGetSymbolAddress(&xh, g_xh);
    cudaGetSymbolAddress(&w1h, g_w1h);
    cudaGetSymbolAddress(&w2h, g_w2h);
    cudaGetSymbolAddress(&xl1h, g_xl1h);
    cudaGetSymbolAddress(&b1h, g_b1h);
    cudaGetSymbolAddress(&hh, g_hh);
    cudaGetSymbolAddress(&xl2h, g_xl2h);
    cudaGetSymbolAddress(&b2h, g_b2h);

    static bool attr_set = false;
    if (!attr_set) {
        cudaFuncSetAttribute(k_gemm_h,
            cudaFuncAttributeMaxDynamicSharedMemorySize, SMEM_H);
        attr_set = true;
    }

    // prep (x cvt + weights + cnt zero) BEFORE scatter (scatter needs cnt=0)
    int total4 = n * FIN / 4;
    int prepTotal = total4 + 384 * 128 + 64 * 128 + n;
    k_prep<<<(prepTotal + 255) / 256, 256>>>(x, total4, n, Wl1, Wr1, res1W,
                                             Wl2, Wr2, res2W, skipW);

    k_scatter<<<(E + n + 255) / 256, 256>>>(ei, E, n);

    int nb128 = (n + 127) / 128;

    // GEMM1: xh[n,128] @ W1h -> xl1h [n,128] fp16, b1h [n,256] fp16
    k_gemm_h<<<dim3(6, nb128), 256, SMEM_H>>>(
        (const __half*)xh, n, (const __half*)w1h,
        (__half*)xl1h, 128, 128, (__half*)b1h, 256,
        bl1, br1, res1b, res1b, 7);

    k_agg1<<<(n + 1) / 2, 64>>>(att1, bias1, ln1g, ln1b, n);

    // GEMM2: hh[n,128] @ W2h -> xl2h [n,16] fp16, b2h [n,48] fp16
    k_gemm_h<<<dim3(1, nb128), 256, SMEM_H>>>(
        (const __half*)hh, n, (const __half*)w2h,
        (__half*)xl2h, 16, 16, (__half*)b2h, 48,
        bl2, br2, res2b, skipb, 4);

    k_agg2<<<(n + 1) / 2, 64>>>(att2, bias2, ln2g, ln2b, outW, outb, out, n);
}